// round 11
// baseline (speedup 1.0000x reference)
#include <cuda_runtime.h>
#include <cuda_bf16.h>
#include <cuda_fp16.h>
#include <math.h>
#include <stdint.h>

#define BB 8
#define NQ 2048
#define NK 2048
#define DD 256
#define NFB 1088             // per-batch folded rows: 576 even (513+pad) + 512 odd
#define NF (BB * NFB)        // 8704
#define QFR 1280             // qf buffer rows per batch (even rows reach 2*639=1278)
typedef __nv_bfloat16 bf16;

// ---------------- static gmem scratch ----------------
__device__ __align__(256) bf16 g_CeH[640 * 576], g_CeL[640 * 576];
__device__ __align__(256) bf16 g_CoH[512 * 512], g_CoL[512 * 512];
__device__ __align__(256) bf16 g_qFh[NF * DD], g_qFl[NF * DD];      // double-folded query
__device__ __align__(256) bf16 g_kH[BB * NK * DD], g_kL[BB * NK * DD];
__device__ __align__(256) bf16 g_wqH[DD * DD], g_wqL[DD * DD];
__device__ __align__(256) bf16 g_wkH[DD * DD], g_wkL[DD * DD];
__device__ __align__(256) bf16 g_qpFTH[DD * NF], g_qpFTL[DD * NF];  // qprojT [256][8704]
__device__ __align__(256) bf16 g_kpH[BB * NK * DD], g_kpL[BB * NK * DD];
__device__ __align__(256) bf16 g_qfH[BB * QFR * DD], g_qfL[BB * QFR * DD];
__device__ __align__(256) __half g_vT[BB * DD * NK];                // key^T fp16
__device__ float g_scores[(size_t)BB * 1024 * NK];
__device__ __align__(256) __half g_pF[(size_t)BB * 1024 * NK];
__device__ float g_op[16 * 1024 * DD];                              // split-K partials

// ---------------- helpers ----------------
__device__ __forceinline__ unsigned smem_u32(const void* p) {
    unsigned a;
    asm("{ .reg .u64 t; cvta.to.shared.u64 t, %1; cvt.u32.u64 %0, t; }"
        : "=r"(a) : "l"(p));
    return a;
}
__device__ __forceinline__ void ldsm4(unsigned r[4], unsigned addr) {
    asm volatile("ldmatrix.sync.aligned.m8n8.x4.shared.b16 {%0,%1,%2,%3}, [%4];"
                 : "=r"(r[0]), "=r"(r[1]), "=r"(r[2]), "=r"(r[3]) : "r"(addr));
}
__device__ __forceinline__ void mma_bf16(float d[4], const unsigned a[4],
                                         unsigned b0, unsigned b1) {
    asm volatile(
        "mma.sync.aligned.m16n8k16.row.col.f32.bf16.bf16.f32 "
        "{%0,%1,%2,%3}, {%4,%5,%6,%7}, {%8,%9}, {%0,%1,%2,%3};"
        : "+f"(d[0]), "+f"(d[1]), "+f"(d[2]), "+f"(d[3])
        : "r"(a[0]), "r"(a[1]), "r"(a[2]), "r"(a[3]), "r"(b0), "r"(b1));
}
__device__ __forceinline__ void mma_f16(float d[4], const unsigned a[4],
                                        unsigned b0, unsigned b1) {
    asm volatile(
        "mma.sync.aligned.m16n8k16.row.col.f32.f16.f16.f32 "
        "{%0,%1,%2,%3}, {%4,%5,%6,%7}, {%8,%9}, {%0,%1,%2,%3};"
        : "+f"(d[0]), "+f"(d[1]), "+f"(d[2]), "+f"(d[3])
        : "r"(a[0]), "r"(a[1]), "r"(a[2]), "r"(a[3]), "r"(b0), "r"(b1));
}
__device__ __forceinline__ void cpa(unsigned dst, const void* src) {
    asm volatile("cp.async.cg.shared.global [%0], [%1], 16;" :: "r"(dst), "l"(src));
}
__device__ __forceinline__ void bsplit(float v, bf16* h, bf16* l) {
    bf16 hv = __float2bfloat16(v);
    *h = hv;
    *l = __float2bfloat16(v - __bfloat162float(hv));
}

// ---------------- prep kernels ----------------
__global__ void split_kernel(const float* __restrict__ x, bf16* __restrict__ h,
                             bf16* __restrict__ l, int n) {
    int i = blockIdx.x * blockDim.x + threadIdx.x;
    if (i < n) bsplit(x[i], &h[i], &l[i]);
}

__global__ void splitW_kernel(const float* __restrict__ Wq,
                              const float* __restrict__ Wk) {
    int i = blockIdx.x * blockDim.x + threadIdx.x;   // 131072
    if (i < 65536) bsplit(Wq[i], &g_wqH[i], &g_wqL[i]);
    else { int j = i - 65536; bsplit(Wk[j], &g_wkH[j], &g_wkL[j]); }
}

// Ce[j][k] = cos(2*pi*(2j)k/2048), j<640 (real j<=512), k<576 (real k<=512)
__global__ void cinitE_kernel() {
    int j = blockIdx.x;
    for (int k = threadIdx.x; k < 576; k += 256) {
        int x = (2 * j * k) & 2047;
        float c = cospif((float)x * (1.0f / 1024.0f));
        bsplit(c, &g_CeH[j * 576 + k], &g_CeL[j * 576 + k]);
    }
}
// Co[j][k] = cos(2*pi*(2j+1)k/2048), j<512, k<512
__global__ void cinitO_kernel() {
    int j = blockIdx.x;
    for (int k = threadIdx.x; k < 512; k += 256) {
        int x = ((2 * j + 1) * k) & 2047;
        float c = cospif((float)x * (1.0f / 1024.0f));
        bsplit(c, &g_CoH[j * 512 + k], &g_CoL[j * 512 + k]);
    }
}

// double fold of query along sequence:
//  f[k] = q[k] + q[2048-k] (k=1..1023), f[0]=q[0], f[1024]=q[1024]
//  even row r=k' (0..575): e[k'] = f[k'] + f[1024-k'] (e[512]=f[512]); pad>512 = 0
//  odd  row r=576+k' (k'=0..511): o[k'] = f[k'] - f[1024-k']
__global__ void foldsplit2_kernel(const float* __restrict__ query) {
    int r = blockIdx.x, b = blockIdx.y, d = threadIdx.x;
    const float* qb = query + (size_t)b * NQ * DD;
    float v;
    if (r < 576) {
        int k = r;
        if (k > 512)      v = 0.0f;
        else if (k == 0)  v = qb[d] + qb[(size_t)1024 * DD + d];
        else if (k == 512) v = qb[(size_t)512 * DD + d] + qb[(size_t)1536 * DD + d];
        else v = qb[(size_t)k * DD + d] + qb[(size_t)(2048 - k) * DD + d]
               + qb[(size_t)(1024 - k) * DD + d] + qb[(size_t)(1024 + k) * DD + d];
    } else {
        int k = r - 576;
        if (k == 0) v = qb[d] - qb[(size_t)1024 * DD + d];
        else v = qb[(size_t)k * DD + d] + qb[(size_t)(2048 - k) * DD + d]
               - qb[(size_t)(1024 - k) * DD + d] - qb[(size_t)(1024 + k) * DD + d];
    }
    size_t idx = ((size_t)b * NFB + r) * DD + d;
    bsplit(v, &g_qFh[idx], &g_qFl[idx]);
}

// key^T as fp16 (value operand for PV)
__global__ void transpose_kernel(const float* __restrict__ key) {
    __shared__ float ts[32][33];
    int b = blockIdx.z, n0 = blockIdx.x * 32, d0 = blockIdx.y * 32;
    const float* kb = key + (size_t)b * NK * DD;
#pragma unroll
    for (int i = 0; i < 4; i++) {
        int r = threadIdx.y + i * 8;
        ts[r][threadIdx.x] = kb[(size_t)(n0 + r) * DD + d0 + threadIdx.x];
    }
    __syncthreads();
#pragma unroll
    for (int i = 0; i < 4; i++) {
        int d = threadIdx.y + i * 8;
        g_vT[(size_t)b * DD * NK + (size_t)(d0 + d) * NK + n0 + threadIdx.x] =
            __float2half_rn(ts[threadIdx.x][d]);
    }
}

// ---------------------------------------------------------------------------
// Split-bf16 mma.sync GEMM, generic CTA tile MTm x NTn (kc=64, 256 threads,
// 8 warps as 2m x 4n).  D[m,n] = sum_k A[m,k]*B[n,k] (+bias[n]).
// OUT: 0 fp32 D, 1 bf16 hi/lo.  Output row = radd + rmul*(logical row).
// ---------------------------------------------------------------------------
template<int OUT, int MT, int NT>
__global__ void __launch_bounds__(256, 1)
gemm_kernel(const bf16* __restrict__ AH, const bf16* __restrict__ AL,
            size_t sA, int rA,
            const bf16* __restrict__ BH, const bf16* __restrict__ BL,
            size_t sB, int rB,
            const float* __restrict__ bias,
            float* __restrict__ D, bf16* __restrict__ DH, bf16* __restrict__ DL,
            size_t sD, int oS, int K, int rmul, int radd)
{
    constexpr int TM   = MT / 32;       // A m16-tiles per warp
    constexpr int NJ   = NT / 32;       // n8-accs per warp
    constexpr int NBL  = NT / 64;       // B ldsm tiles per warp per ks
    constexpr int ABY  = MT * 128;      // A plane bytes per stage
    constexpr int BBY  = NT * 128;
    constexpr int BUFS = 2 * ABY + 2 * BBY;

    extern __shared__ char sm[];
    const unsigned smb = smem_u32(sm);
    const int tid = threadIdx.x;
    const int lane = tid & 31;
    const int wid = tid >> 5;
    const int m0 = blockIdx.y * MT;
    const int n0 = blockIdx.x * NT;
    const int b  = blockIdx.z;
    const int wm = (wid & 1) * (MT / 2);
    const int wn = (wid >> 1) * (NT / 4);
    const int l15 = lane & 15;
    const int lh = lane >> 4;

    const bf16* AHb = AH + b * sA;
    const bf16* ALb = AL + b * sA;
    const bf16* BHb = BH + b * sB;
    const bf16* BLb = BL + b * sB;

    float acc[TM][NJ][4];
#pragma unroll
    for (int t = 0; t < TM; t++)
#pragma unroll
        for (int j = 0; j < NJ; j++)
#pragma unroll
            for (int i = 0; i < 4; i++) acc[t][j][i] = 0.0f;

    const int rw = tid >> 3, ch = tid & 7;

    auto ISSUE = [&](int c) {
        const int ke = (c << 6) + ch * 8;
        const unsigned bufb = smb + (c & 1) * BUFS;
#pragma unroll
        for (int it = 0; it < MT / 32; it++) {
            int r = rw + it * 32;
            unsigned so = bufb + r * 128 + ((ch ^ (r & 7)) << 4);
            size_t go = (size_t)(m0 + r) * rA + ke;
            cpa(so, AHb + go);
            cpa(so + ABY, ALb + go);
        }
#pragma unroll
        for (int it = 0; it < NT / 32; it++) {
            int r = rw + it * 32;
            unsigned so = bufb + 2 * ABY + r * 128 + ((ch ^ (r & 7)) << 4);
            size_t go = (size_t)(n0 + r) * rB + ke;
            cpa(so, BHb + go);
            cpa(so + BBY, BLb + go);
        }
        asm volatile("cp.async.commit_group;" ::: "memory");
    };

    const int NC = K >> 6;
    ISSUE(0);
#pragma unroll 1
    for (int c = 0; c < NC; c++) {
        if (c + 1 < NC) {
            ISSUE(c + 1);
            asm volatile("cp.async.wait_group 1;" ::: "memory");
        } else {
            asm volatile("cp.async.wait_group 0;" ::: "memory");
        }
        __syncthreads();
        const unsigned ab = smb + (c & 1) * BUFS;
#pragma unroll
        for (int ks = 0; ks < 4; ks++) {
            const unsigned cc = (unsigned)(ks * 2 + lh);
            unsigned Ah[TM][4], Al[TM][4], Bh[NBL][4], Bl[NBL][4];
#pragma unroll
            for (int t = 0; t < TM; t++) {
                int row = wm + 16 * t + l15;
                unsigned so = ab + row * 128 + ((cc ^ (row & 7)) << 4);
                ldsm4(Ah[t], so);
                ldsm4(Al[t], so + ABY);
            }
#pragma unroll
            for (int nt = 0; nt < NBL; nt++) {
                int row = wn + 16 * nt + l15;
                unsigned so = ab + 2 * ABY + row * 128 + ((cc ^ (row & 7)) << 4);
                ldsm4(Bh[nt], so);
                ldsm4(Bl[nt], so + BBY);
            }
#pragma unroll
            for (int t = 0; t < TM; t++)
#pragma unroll
                for (int nt = 0; nt < NBL; nt++)
#pragma unroll
                    for (int s = 0; s < 2; s++) {
                        int j = nt * 2 + s;
                        mma_bf16(acc[t][j], Ah[t], Bh[nt][s], Bh[nt][2 + s]);
                        mma_bf16(acc[t][j], Ah[t], Bl[nt][s], Bl[nt][2 + s]);
                        mma_bf16(acc[t][j], Al[t], Bh[nt][s], Bh[nt][2 + s]);
                    }
        }
        __syncthreads();
    }

    // ---- epilogue ----
#pragma unroll
    for (int t = 0; t < TM; t++) {
#pragma unroll
        for (int j = 0; j < NJ; j++) {
            int jr = m0 + wm + 16 * t + (lane >> 2);
            int col = n0 + wn + 8 * j + 2 * (lane & 3);
            size_t ro0 = (size_t)(radd + rmul * jr);
            size_t ro1 = (size_t)(radd + rmul * (jr + 8));
            float b0v = 0.0f, b1v = 0.0f;
            if (bias) { b0v = __ldg(&bias[col]); b1v = __ldg(&bias[col + 1]); }
            float v0 = acc[t][j][0] + b0v, v1 = acc[t][j][1] + b1v;
            float v2 = acc[t][j][2] + b0v, v3 = acc[t][j][3] + b1v;
            if (OUT == 0) {
                float* Dp = D + b * sD;
                *(float2*)(Dp + ro0 * oS + col) = make_float2(v0, v1);
                *(float2*)(Dp + ro1 * oS + col) = make_float2(v2, v3);
            } else {
                bf16* Hp = DH + b * sD;
                bf16* Lp = DL + b * sD;
                __nv_bfloat162 h01, h23, l01, l23;
                h01.x = __float2bfloat16(v0); h01.y = __float2bfloat16(v1);
                h23.x = __float2bfloat16(v2); h23.y = __float2bfloat16(v3);
                l01.x = __float2bfloat16(v0 - __bfloat162float(h01.x));
                l01.y = __float2bfloat16(v1 - __bfloat162float(h01.y));
                l23.x = __float2bfloat16(v2 - __bfloat162float(h23.x));
                l23.y = __float2bfloat16(v3 - __bfloat162float(h23.y));
                *(__nv_bfloat162*)(Hp + ro0 * oS + col) = h01;
                *(__nv_bfloat162*)(Lp + ro0 * oS + col) = l01;
                *(__nv_bfloat162*)(Hp + ro1 * oS + col) = h23;
                *(__nv_bfloat162*)(Lp + ro1 * oS + col) = l23;
            }
        }
    }
}

// ---------------------------------------------------------------------------
// fp16 single-pass GEMM for PV (post-softmax).  CTA 128x128, kc=64, 256 thr,
// 8 warps 4m x 2n (32x64).  Split-K=2: bz = b + 8*ks.
// ---------------------------------------------------------------------------
__global__ void __launch_bounds__(256, 1)
hgemm(const __half* __restrict__ A, size_t sAb, int rA,
      const __half* __restrict__ B, size_t sBb, int rB,
      float* __restrict__ D, size_t sD, int oS, int K)
{
    extern __shared__ char sm[];
    const unsigned smb = smem_u32(sm);
    const int tid = threadIdx.x;
    const int lane = tid & 31;
    const int wid = tid >> 5;
    const int m0 = blockIdx.y * 128;
    const int n0 = blockIdx.x * 128;
    const int bz = blockIdx.z;
    const int b  = bz & 7;
    const int koff = (bz >> 3) * K;
    const int wm = (wid & 3) * 32;
    const int wn = (wid >> 2) * 64;
    const int l15 = lane & 15;
    const int lh = lane >> 4;

    const __half* Ab = A + (size_t)b * sAb + koff;
    const __half* Bb = B + (size_t)b * sBb + koff;

    float acc[2][8][4];
#pragma unroll
    for (int t = 0; t < 2; t++)
#pragma unroll
        for (int j = 0; j < 8; j++)
#pragma unroll
            for (int i = 0; i < 4; i++) acc[t][j][i] = 0.0f;

    const int rw = tid >> 3, ch = tid & 7;

    auto ISSUE = [&](int c) {
        const int ke = (c << 6) + ch * 8;
        const unsigned sb = smb + (c & 1) * 32768;
#pragma unroll
        for (int it = 0; it < 4; it++) {
            int r = rw + it * 32;
            unsigned so = sb + r * 128 + ((ch ^ (r & 7)) << 4);
            cpa(so, Ab + (size_t)(m0 + r) * rA + ke);
            cpa(so + 16384, Bb + (size_t)(n0 + r) * rB + ke);
        }
        asm volatile("cp.async.commit_group;" ::: "memory");
    };

    const int NC = K >> 6;
    ISSUE(0);
#pragma unroll 1
    for (int c = 0; c < NC; c++) {
        if (c + 1 < NC) {
            ISSUE(c + 1);
            asm volatile("cp.async.wait_group 1;" ::: "memory");
        } else {
            asm volatile("cp.async.wait_group 0;" ::: "memory");
        }
        __syncthreads();
        const unsigned ab = smb + (c & 1) * 32768;
#pragma unroll
        for (int ks = 0; ks < 4; ks++) {
            const unsigned cc = (unsigned)(ks * 2 + lh);
            unsigned Af[2][4], Bf[4][4];
#pragma unroll
            for (int t = 0; t < 2; t++) {
                int row = wm + 16 * t + l15;
                ldsm4(Af[t], ab + row * 128 + ((cc ^ (row & 7)) << 4));
            }
#pragma unroll
            for (int nt = 0; nt < 4; nt++) {
                int row = wn + 16 * nt + l15;
                ldsm4(Bf[nt], ab + 16384 + row * 128 + ((cc ^ (row & 7)) << 4));
            }
#pragma unroll
            for (int t = 0; t < 2; t++)
#pragma unroll
                for (int nt = 0; nt < 4; nt++)
#pragma unroll
                    for (int s = 0; s < 2; s++)
                        mma_f16(acc[t][nt * 2 + s], Af[t], Bf[nt][s], Bf[nt][2 + s]);
        }
        __syncthreads();
    }

    float* Dp = D + (size_t)bz * sD;
#pragma unroll
    for (int t = 0; t < 2; t++) {
#pragma unroll
        for (int j = 0; j < 8; j++) {
            int r0 = m0 + wm + 16 * t + (lane >> 2);
            int col = n0 + wn + 8 * j + 2 * (lane & 3);
            *(float2*)(Dp + (size_t)r0 * oS + col) =
                make_float2(acc[t][j][0], acc[t][j][1]);
            *(float2*)(Dp + (size_t)(r0 + 8) * oS + col) =
                make_float2(acc[t][j][2], acc[t][j][3]);
        }
    }
}

// ---------------------------------------------------------------------------
// Row softmax over NK with scale 1/16; emits probs as fp16
// ---------------------------------------------------------------------------
__global__ void softmax_kernel(const float* __restrict__ s, __half* __restrict__ pF) {
    size_t row = blockIdx.x;
    const float* p = s + row * (size_t)NK;
    int t = threadIdx.x;
    float v[8];
#pragma unroll
    for (int i = 0; i < 8; i++) v[i] = p[t + 256 * i] * 0.0625f;
    float mx = v[0];
#pragma unroll
    for (int i = 1; i < 8; i++) mx = fmaxf(mx, v[i]);
#pragma unroll
    for (int o = 16; o > 0; o >>= 1) mx = fmaxf(mx, __shfl_xor_sync(0xffffffffu, mx, o));
    __shared__ float redm[8], reds[8];
    if ((t & 31) == 0) redm[t >> 5] = mx;
    __syncthreads();
    float m2 = redm[0];
#pragma unroll
    for (int i = 1; i < 8; i++) m2 = fmaxf(m2, redm[i]);
    float sum = 0.0f;
#pragma unroll
    for (int i = 0; i < 8; i++) { v[i] = __expf(v[i] - m2); sum += v[i]; }
#pragma unroll
    for (int o = 16; o > 0; o >>= 1) sum += __shfl_xor_sync(0xffffffffu, sum, o);
    if ((t & 31) == 0) reds[t >> 5] = sum;
    __syncthreads();
    float s2 = 0.0f;
#pragma unroll
    for (int i = 0; i < 8; i++) s2 += reds[i];
    float inv = 1.0f / s2;
    size_t base = row * (size_t)NK + t;
#pragma unroll
    for (int i = 0; i < 8; i++)
        pF[base + 256 * i] = __float2half_rn(v[i] * inv);
}

// ---------------------------------------------------------------------------
// attention row m=1024 (self-mirror row), full fp32.  grid(BB), 256 threads.
// ---------------------------------------------------------------------------
__global__ void row1024_kernel(const float* __restrict__ key, float* __restrict__ out) {
    __shared__ float qrow[256];
    __shared__ float lg[2048];
    __shared__ float redm[8], reds[8];
    int b = blockIdx.x, t = threadIdx.x;
    size_t qoff = ((size_t)b * QFR + 1024) * DD + t;
    qrow[t] = __bfloat162float(g_qfH[qoff]) + __bfloat162float(g_qfL[qoff]);
    __syncthreads();

    int w = t >> 5, ln = t & 31;
    for (int n = w; n < 2048; n += 8) {
        const bf16* kh = g_kpH + ((size_t)b * NK + n) * DD;
        const bf16* kl = g_kpL + ((size_t)b * NK + n) * DD;
        float a = 0.0f;
        for (int d = ln; d < 256; d += 32)
            a += qrow[d] * (__bfloat162float(kh[d]) + __bfloat162float(kl[d]));
#pragma unroll
        for (int o = 16; o > 0; o >>= 1) a += __shfl_xor_sync(0xffffffffu, a, o);
        if (ln == 0) lg[n] = a * 0.0625f;
    }
    __syncthreads();

    float mx = -INFINITY;
#pragma unroll
    for (int i = 0; i < 8; i++) mx = fmaxf(mx, lg[t + 256 * i]);
#pragma unroll
    for (int o = 16; o > 0; o >>= 1) mx = fmaxf(mx, __shfl_xor_sync(0xffffffffu, mx, o));
    if (ln == 0) redm[w] = mx;
    __syncthreads();
    float m2 = redm[0];
#pragma unroll
    for (int i = 1; i < 8; i++) m2 = fmaxf(m2, redm[i]);

    float s = 0.0f;
#pragma unroll
    for (int i = 0; i < 8; i++) {
        float e = __expf(lg[t + 256 * i] - m2);
        lg[t + 256 * i] = e;
        s += e;
    }
#pragma unroll
    for (int o = 16; o > 0; o >>= 1) s += __shfl_xor_sync(0xffffffffu, s, o);
    if (ln == 0) reds[w] = s;
    __syncthreads();
    float s2 = 0.0f;
#pragma unroll
    for (int i = 0; i < 8; i++) s2 += reds[i];
    float inv = 1.0f / s2;

    float acc = 0.0f;
    const float* kb = key + (size_t)b * NK * DD;
    for (int n = 0; n < 2048; n++)
        acc += lg[n] * kb[(size_t)n * DD + t];
    out[((size_t)b * NQ + 1024) * DD + t] = acc * inv;
}

// ---------------------------------------------------------------------------
// combine split-K partials + mirror: out[b][m]=v, out[b][2048-m]=v (m=1..1023)
// ---------------------------------------------------------------------------
__global__ void combine_kernel(const float* __restrict__ op, float* __restrict__ out) {
    int m = blockIdx.x, b = blockIdx.y, d = threadIdx.x;
    size_t src = ((size_t)b * 1024 + m) * DD + d;
    float v = op[src] + op[src + (size_t)8 * 1024 * DD];
    out[((size_t)b * NQ + m) * DD + d] = v;
    if (m >= 1)
        out[((size_t)b * NQ + 2048 - m) * DD + d] = v;
}

// ---------------------------------------------------------------------------
extern "C" void kernel_launch(void* const* d_in, const int* in_sizes, int n_in,
                              void* d_out, int out_size) {
    const float* query = (const float*)d_in[0];
    const float* key   = (const float*)d_in[1];
    const float* Wq    = (const float*)d_in[2];
    const float* bq    = (const float*)d_in[3];
    const float* Wk    = (const float*)d_in[4];
    const float* bk    = (const float*)d_in[5];
    float* out = (float*)d_out;

#define SYM(p, s) void* p; cudaGetSymbolAddress(&p, s)
    SYM(CeH, g_CeH); SYM(CeL, g_CeL); SYM(CoH, g_CoH); SYM(CoL, g_CoL);
    SYM(qFh, g_qFh); SYM(qFl, g_qFl);
    SYM(kH, g_kH);   SYM(kL, g_kL);
    SYM(wqH, g_wqH); SYM(wqL, g_wqL); SYM(wkH, g_wkH); SYM(wkL, g_wkL);
    SYM(qpFTH, g_qpFTH); SYM(qpFTL, g_qpFTL);
    SYM(kpH, g_kpH); SYM(kpL, g_kpL);
    SYM(qfH, g_qfH); SYM(qfL, g_qfL);
    SYM(vT, g_vT);   SYM(pF, g_pF);
    SYM(sc, g_scores); SYM(op, g_op);
#undef SYM

    const int SM_64_256  = 2 * (2 * 64 * 128 + 2 * 256 * 128);   // 163840
    const int SM_128_256 = 2 * (2 * 128 * 128 + 2 * 256 * 128);  // 196608
    const int SM_64_128  = 2 * (2 * 64 * 128 + 2 * 128 * 128);   // 98304
    const int SMH = 65536;
    cudaFuncSetAttribute((const void*)gemm_kernel<1,64,256>,  cudaFuncAttributeMaxDynamicSharedMemorySize, SM_64_256);
    cudaFuncSetAttribute((const void*)gemm_kernel<1,128,256>, cudaFuncAttributeMaxDynamicSharedMemorySize, SM_128_256);
    cudaFuncSetAttribute((const void*)gemm_kernel<0,128,256>, cudaFuncAttributeMaxDynamicSharedMemorySize, SM_128_256);
    cudaFuncSetAttribute((const void*)gemm_kernel<1,64,128>,  cudaFuncAttributeMaxDynamicSharedMemorySize, SM_64_128);
    cudaFuncSetAttribute((const void*)hgemm, cudaFuncAttributeMaxDynamicSharedMemorySize, SMH);

    // preps
    cinitE_kernel<<<640, 256>>>();
    cinitO_kernel<<<512, 256>>>();
    foldsplit2_kernel<<<dim3(NFB, BB), 256>>>(query);
    split_kernel<<<16384, 256>>>(key, (bf16*)kH, (bf16*)kL, BB * NK * DD);
    splitW_kernel<<<512, 256>>>(Wq, Wk);
    transpose_kernel<<<dim3(NK / 32, DD / 32, BB), dim3(32, 8)>>>(key);

    // G1: qpFT[d, n] = Wq @ qF^T   (M=256, N=8704, K=256), 64-row tiles
    gemm_kernel<1,64,256><<<dim3(NF / 256, 4, 1), 256, SM_64_256>>>(
        (bf16*)wqH, (bf16*)wqL, 0, DD, (bf16*)qFh, (bf16*)qFl, 0, DD,
        nullptr, nullptr, (bf16*)qpFTH, (bf16*)qpFTL, 0, NF, DD, 1, 0);
    // G2: kproj = key @ Wk^T + bk  (M=16384, N=256, K=256)
    gemm_kernel<1,128,256><<<dim3(1, 128, 1), 256, SM_128_256>>>(
        (bf16*)kH, (bf16*)kL, 0, DD, (bf16*)wkH, (bf16*)wkL, 0, DD,
        bk, nullptr, (bf16*)kpH, (bf16*)kpL, 0, DD, DD, 1, 0);
    // G3e: qf[2j] = Ce @ qpFT_e^T + bq   (per b: M=640, N=256, K=576)
    gemm_kernel<1,64,128><<<dim3(2, 10, BB), 256, SM_64_128>>>(
        (bf16*)CeH, (bf16*)CeL, 0, 576, (bf16*)qpFTH, (bf16*)qpFTL, NFB, NF,
        bq, nullptr, (bf16*)qfH, (bf16*)qfL, (size_t)QFR * DD, DD, 576, 2, 0);
    // G3o: qf[2j+1] = Co @ qpFT_o^T + bq (per b: M=512, N=256, K=512)
    gemm_kernel<1,64,128><<<dim3(2, 8, BB), 256, SM_64_128>>>(
        (bf16*)CoH, (bf16*)CoL, 0, 512,
        (bf16*)qpFTH + 576, (bf16*)qpFTL + 576, NFB, NF,
        bq, nullptr, (bf16*)qfH, (bf16*)qfL, (size_t)QFR * DD, DD, 512, 2, 1);
    // G4: scores = qf @ kproj^T   (per b: M=1024, N=2048, K=256)
    gemm_kernel<0,128,256><<<dim3(8, 8, BB), 256, SM_128_256>>>(
        (bf16*)qfH, (bf16*)qfL, (size_t)QFR * DD, DD,
        (bf16*)kpH, (bf16*)kpL, (size_t)NK * DD, DD,
        nullptr, (float*)sc, nullptr, nullptr, (size_t)1024 * NK, NK, DD, 1, 0);
    // softmax -> fp16 probs
    softmax_kernel<<<BB * 1024, 256>>>((const float*)sc, (__half*)pF);
    // G5: partial out = probs @ vT^T (fp16, split-K=2)
    hgemm<<<dim3(2, 8, 16), 256, SMH>>>(
        (const __half*)pF, (size_t)1024 * NK, NK,
        (const __half*)vT, (size_t)DD * NK, NK,
        (float*)op, (size_t)1024 * DD, DD, 1024);
    // combine + mirror, then the self-mirror row 1024
    combine_kernel<<<dim3(1024, BB), 256>>>((const float*)op, out);
    row1024_kernel<<<BB, 256>>>(key, out);
}

// round 12
// speedup vs baseline: 3.2841x; 3.2841x over previous
#include <cuda_runtime.h>
#include <cuda_bf16.h>
#include <cuda_fp16.h>
#include <math.h>
#include <stdint.h>

#define BB 8
#define NQ 2048
#define NK 2048
#define DD 256
#define MP 1152              // downstream row count (9*128), rows 0..1024 real+usable
#define NFB 1088             // per-batch folded rows: 576 even + 512 odd
#define NF (BB * NFB)        // 8704
#define QFR 1280             // qf buffer rows per batch
typedef __nv_bfloat16 bf16;

// ---------------- static gmem scratch ----------------
__device__ __align__(256) bf16 g_CeH[640 * 576], g_CeL[640 * 576];
__device__ __align__(256) bf16 g_CoH[576 * 512], g_CoL[576 * 512];
__device__ __align__(256) bf16 g_qFh[NF * DD], g_qFl[NF * DD];      // double-folded query
__device__ __align__(256) bf16 g_kH[BB * NK * DD], g_kL[BB * NK * DD];
__device__ __align__(256) bf16 g_wqH[DD * DD], g_wqL[DD * DD];
__device__ __align__(256) bf16 g_wkH[DD * DD], g_wkL[DD * DD];
__device__ __align__(256) bf16 g_qpFTH[DD * NF], g_qpFTL[DD * NF];  // qprojT [256][8704]
__device__ __align__(256) bf16 g_kpH[BB * NK * DD], g_kpL[BB * NK * DD];
__device__ __align__(256) bf16 g_qfH[BB * QFR * DD], g_qfL[BB * QFR * DD];
__device__ __align__(256) __half g_vT[BB * DD * NK];                // key^T fp16
__device__ float g_scores[(size_t)BB * MP * NK];
__device__ __align__(256) __half g_pF[(size_t)BB * MP * NK];
__device__ float g_op[16 * MP * DD];                                // split-K partials

// ---------------- helpers ----------------
__device__ __forceinline__ unsigned smem_u32(const void* p) {
    unsigned a;
    asm("{ .reg .u64 t; cvta.to.shared.u64 t, %1; cvt.u32.u64 %0, t; }"
        : "=r"(a) : "l"(p));
    return a;
}
__device__ __forceinline__ void ldsm4(unsigned r[4], unsigned addr) {
    asm volatile("ldmatrix.sync.aligned.m8n8.x4.shared.b16 {%0,%1,%2,%3}, [%4];"
                 : "=r"(r[0]), "=r"(r[1]), "=r"(r[2]), "=r"(r[3]) : "r"(addr));
}
__device__ __forceinline__ void mma_bf16(float d[4], const unsigned a[4],
                                         unsigned b0, unsigned b1) {
    asm volatile(
        "mma.sync.aligned.m16n8k16.row.col.f32.bf16.bf16.f32 "
        "{%0,%1,%2,%3}, {%4,%5,%6,%7}, {%8,%9}, {%0,%1,%2,%3};"
        : "+f"(d[0]), "+f"(d[1]), "+f"(d[2]), "+f"(d[3])
        : "r"(a[0]), "r"(a[1]), "r"(a[2]), "r"(a[3]), "r"(b0), "r"(b1));
}
__device__ __forceinline__ void mma_f16(float d[4], const unsigned a[4],
                                        unsigned b0, unsigned b1) {
    asm volatile(
        "mma.sync.aligned.m16n8k16.row.col.f32.f16.f16.f32 "
        "{%0,%1,%2,%3}, {%4,%5,%6,%7}, {%8,%9}, {%0,%1,%2,%3};"
        : "+f"(d[0]), "+f"(d[1]), "+f"(d[2]), "+f"(d[3])
        : "r"(a[0]), "r"(a[1]), "r"(a[2]), "r"(a[3]), "r"(b0), "r"(b1));
}
__device__ __forceinline__ void cpa(unsigned dst, const void* src) {
    asm volatile("cp.async.cg.shared.global [%0], [%1], 16;" :: "r"(dst), "l"(src));
}
__device__ __forceinline__ void bsplit(float v, bf16* h, bf16* l) {
    bf16 hv = __float2bfloat16(v);
    *h = hv;
    *l = __float2bfloat16(v - __bfloat162float(hv));
}

// ---------------- prep kernels ----------------
__global__ void split_kernel(const float* __restrict__ x, bf16* __restrict__ h,
                             bf16* __restrict__ l, int n) {
    int i = blockIdx.x * blockDim.x + threadIdx.x;
    if (i < n) bsplit(x[i], &h[i], &l[i]);
}

__global__ void splitW_kernel(const float* __restrict__ Wq,
                              const float* __restrict__ Wk) {
    int i = blockIdx.x * blockDim.x + threadIdx.x;   // 131072
    if (i < 65536) bsplit(Wq[i], &g_wqH[i], &g_wqL[i]);
    else { int j = i - 65536; bsplit(Wk[j], &g_wkH[j], &g_wkL[j]); }
}

// Ce[j][k] = cos(2*pi*(2j)k/2048), j<640, k<576 (real k<=512, rest harmless)
__global__ void cinitE_kernel() {
    int j = blockIdx.x;
    for (int k = threadIdx.x; k < 576; k += 256) {
        int x = (2 * j * k) & 2047;
        float c = cospif((float)x * (1.0f / 1024.0f));
        bsplit(c, &g_CeH[j * 576 + k], &g_CeL[j * 576 + k]);
    }
}
// Co[j][k] = cos(2*pi*(2j+1)k/2048), j<576 (odd m up to 1151), k<512
__global__ void cinitO_kernel() {
    int j = blockIdx.x;
    for (int k = threadIdx.x; k < 512; k += 256) {
        int x = ((2 * j + 1) * k) & 2047;
        float c = cospif((float)x * (1.0f / 1024.0f));
        bsplit(c, &g_CoH[j * 512 + k], &g_CoL[j * 512 + k]);
    }
}

// double fold of query along sequence (see R11 derivation):
//  even row r=k' (0..575): e[k'] = f[k'] + f[1024-k'] (e[512]=f[512]); pad>512 = 0
//  odd  row r=576+k' (k'=0..511): o[k'] = f[k'] - f[1024-k']
__global__ void foldsplit2_kernel(const float* __restrict__ query) {
    int r = blockIdx.x, b = blockIdx.y, d = threadIdx.x;
    const float* qb = query + (size_t)b * NQ * DD;
    float v;
    if (r < 576) {
        int k = r;
        if (k > 512)      v = 0.0f;
        else if (k == 0)  v = qb[d] + qb[(size_t)1024 * DD + d];
        else if (k == 512) v = qb[(size_t)512 * DD + d] + qb[(size_t)1536 * DD + d];
        else v = qb[(size_t)k * DD + d] + qb[(size_t)(2048 - k) * DD + d]
               + qb[(size_t)(1024 - k) * DD + d] + qb[(size_t)(1024 + k) * DD + d];
    } else {
        int k = r - 576;
        if (k == 0) v = qb[d] - qb[(size_t)1024 * DD + d];
        else v = qb[(size_t)k * DD + d] + qb[(size_t)(2048 - k) * DD + d]
               - qb[(size_t)(1024 - k) * DD + d] - qb[(size_t)(1024 + k) * DD + d];
    }
    size_t idx = ((size_t)b * NFB + r) * DD + d;
    bsplit(v, &g_qFh[idx], &g_qFl[idx]);
}

// key^T as fp16 (value operand for PV)
__global__ void transpose_kernel(const float* __restrict__ key) {
    __shared__ float ts[32][33];
    int b = blockIdx.z, n0 = blockIdx.x * 32, d0 = blockIdx.y * 32;
    const float* kb = key + (size_t)b * NK * DD;
#pragma unroll
    for (int i = 0; i < 4; i++) {
        int r = threadIdx.y + i * 8;
        ts[r][threadIdx.x] = kb[(size_t)(n0 + r) * DD + d0 + threadIdx.x];
    }
    __syncthreads();
#pragma unroll
    for (int i = 0; i < 4; i++) {
        int d = threadIdx.y + i * 8;
        g_vT[(size_t)b * DD * NK + (size_t)(d0 + d) * NK + n0 + threadIdx.x] =
            __float2half_rn(ts[threadIdx.x][d]);
    }
}

// ---------------------------------------------------------------------------
// Split-bf16 mma.sync GEMM, generic CTA tile MTm x NTn (kc=64, 256 threads,
// 8 warps as 2m x 4n).  D[m,n] = sum_k A[m,k]*B[n,k] (+bias[n]).
// OUT: 0 fp32 D, 1 bf16 hi/lo.  Output row = radd + rmul*(logical row).
// ---------------------------------------------------------------------------
template<int OUT, int MT, int NT>
__global__ void __launch_bounds__(256, 1)
gemm_kernel(const bf16* __restrict__ AH, const bf16* __restrict__ AL,
            size_t sA, int rA,
            const bf16* __restrict__ BH, const bf16* __restrict__ BL,
            size_t sB, int rB,
            const float* __restrict__ bias,
            float* __restrict__ D, bf16* __restrict__ DH, bf16* __restrict__ DL,
            size_t sD, int oS, int K, int rmul, int radd)
{
    constexpr int TM   = MT / 32;
    constexpr int NJ   = NT / 32;
    constexpr int NBL  = NT / 64;
    constexpr int ABY  = MT * 128;
    constexpr int BBY  = NT * 128;
    constexpr int BUFS = 2 * ABY + 2 * BBY;

    extern __shared__ char sm[];
    const unsigned smb = smem_u32(sm);
    const int tid = threadIdx.x;
    const int lane = tid & 31;
    const int wid = tid >> 5;
    const int m0 = blockIdx.y * MT;
    const int n0 = blockIdx.x * NT;
    const int b  = blockIdx.z;
    const int wm = (wid & 1) * (MT / 2);
    const int wn = (wid >> 1) * (NT / 4);
    const int l15 = lane & 15;
    const int lh = lane >> 4;

    const bf16* AHb = AH + b * sA;
    const bf16* ALb = AL + b * sA;
    const bf16* BHb = BH + b * sB;
    const bf16* BLb = BL + b * sB;

    float acc[TM][NJ][4];
#pragma unroll
    for (int t = 0; t < TM; t++)
#pragma unroll
        for (int j = 0; j < NJ; j++)
#pragma unroll
            for (int i = 0; i < 4; i++) acc[t][j][i] = 0.0f;

    const int rw = tid >> 3, ch = tid & 7;

    auto ISSUE = [&](int c) {
        const int ke = (c << 6) + ch * 8;
        const unsigned bufb = smb + (c & 1) * BUFS;
#pragma unroll
        for (int it = 0; it < MT / 32; it++) {
            int r = rw + it * 32;
            unsigned so = bufb + r * 128 + ((ch ^ (r & 7)) << 4);
            size_t go = (size_t)(m0 + r) * rA + ke;
            cpa(so, AHb + go);
            cpa(so + ABY, ALb + go);
        }
#pragma unroll
        for (int it = 0; it < NT / 32; it++) {
            int r = rw + it * 32;
            unsigned so = bufb + 2 * ABY + r * 128 + ((ch ^ (r & 7)) << 4);
            size_t go = (size_t)(n0 + r) * rB + ke;
            cpa(so, BHb + go);
            cpa(so + BBY, BLb + go);
        }
        asm volatile("cp.async.commit_group;" ::: "memory");
    };

    const int NC = K >> 6;
    ISSUE(0);
#pragma unroll 1
    for (int c = 0; c < NC; c++) {
        if (c + 1 < NC) {
            ISSUE(c + 1);
            asm volatile("cp.async.wait_group 1;" ::: "memory");
        } else {
            asm volatile("cp.async.wait_group 0;" ::: "memory");
        }
        __syncthreads();
        const unsigned ab = smb + (c & 1) * BUFS;
#pragma unroll
        for (int ks = 0; ks < 4; ks++) {
            const unsigned cc = (unsigned)(ks * 2 + lh);
            unsigned Ah[TM][4], Al[TM][4], Bh[NBL][4], Bl[NBL][4];
#pragma unroll
            for (int t = 0; t < TM; t++) {
                int row = wm + 16 * t + l15;
                unsigned so = ab + row * 128 + ((cc ^ (row & 7)) << 4);
                ldsm4(Ah[t], so);
                ldsm4(Al[t], so + ABY);
            }
#pragma unroll
            for (int nt = 0; nt < NBL; nt++) {
                int row = wn + 16 * nt + l15;
                unsigned so = ab + 2 * ABY + row * 128 + ((cc ^ (row & 7)) << 4);
                ldsm4(Bh[nt], so);
                ldsm4(Bl[nt], so + BBY);
            }
#pragma unroll
            for (int t = 0; t < TM; t++)
#pragma unroll
                for (int nt = 0; nt < NBL; nt++)
#pragma unroll
                    for (int s = 0; s < 2; s++) {
                        int j = nt * 2 + s;
                        mma_bf16(acc[t][j], Ah[t], Bh[nt][s], Bh[nt][2 + s]);
                        mma_bf16(acc[t][j], Ah[t], Bl[nt][s], Bl[nt][2 + s]);
                        mma_bf16(acc[t][j], Al[t], Bh[nt][s], Bh[nt][2 + s]);
                    }
        }
        __syncthreads();
    }

    // ---- epilogue ----
#pragma unroll
    for (int t = 0; t < TM; t++) {
#pragma unroll
        for (int j = 0; j < NJ; j++) {
            int jr = m0 + wm + 16 * t + (lane >> 2);
            int col = n0 + wn + 8 * j + 2 * (lane & 3);
            size_t ro0 = (size_t)(radd + rmul * jr);
            size_t ro1 = (size_t)(radd + rmul * (jr + 8));
            float b0v = 0.0f, b1v = 0.0f;
            if (bias) { b0v = __ldg(&bias[col]); b1v = __ldg(&bias[col + 1]); }
            float v0 = acc[t][j][0] + b0v, v1 = acc[t][j][1] + b1v;
            float v2 = acc[t][j][2] + b0v, v3 = acc[t][j][3] + b1v;
            if (OUT == 0) {
                float* Dp = D + b * sD;
                *(float2*)(Dp + ro0 * oS + col) = make_float2(v0, v1);
                *(float2*)(Dp + ro1 * oS + col) = make_float2(v2, v3);
            } else {
                bf16* Hp = DH + b * sD;
                bf16* Lp = DL + b * sD;
                __nv_bfloat162 h01, h23, l01, l23;
                h01.x = __float2bfloat16(v0); h01.y = __float2bfloat16(v1);
                h23.x = __float2bfloat16(v2); h23.y = __float2bfloat16(v3);
                l01.x = __float2bfloat16(v0 - __bfloat162float(h01.x));
                l01.y = __float2bfloat16(v1 - __bfloat162float(h01.y));
                l23.x = __float2bfloat16(v2 - __bfloat162float(h23.x));
                l23.y = __float2bfloat16(v3 - __bfloat162float(h23.y));
                *(__nv_bfloat162*)(Hp + ro0 * oS + col) = h01;
                *(__nv_bfloat162*)(Lp + ro0 * oS + col) = l01;
                *(__nv_bfloat162*)(Hp + ro1 * oS + col) = h23;
                *(__nv_bfloat162*)(Lp + ro1 * oS + col) = l23;
            }
        }
    }
}

// ---------------------------------------------------------------------------
// fp16 single-pass GEMM for PV (post-softmax).  CTA 128x128, kc=64, 256 thr,
// 8 warps 4m x 2n (32x64).  Split-K=2: bz = b + 8*ks.
// ---------------------------------------------------------------------------
__global__ void __launch_bounds__(256, 1)
hgemm(const __half* __restrict__ A, size_t sAb, int rA,
      const __half* __restrict__ B, size_t sBb, int rB,
      float* __restrict__ D, size_t sD, int oS, int K)
{
    extern __shared__ char sm[];
    const unsigned smb = smem_u32(sm);
    const int tid = threadIdx.x;
    const int lane = tid & 31;
    const int wid = tid >> 5;
    const int m0 = blockIdx.y * 128;
    const int n0 = blockIdx.x * 128;
    const int bz = blockIdx.z;
    const int b  = bz & 7;
    const int koff = (bz >> 3) * K;
    const int wm = (wid & 3) * 32;
    const int wn = (wid >> 2) * 64;
    const int l15 = lane & 15;
    const int lh = lane >> 4;

    const __half* Ab = A + (size_t)b * sAb + koff;
    const __half* Bb = B + (size_t)b * sBb + koff;

    float acc[2][8][4];
#pragma unroll
    for (int t = 0; t < 2; t++)
#pragma unroll
        for (int j = 0; j < 8; j++)
#pragma unroll
            for (int i = 0; i < 4; i++) acc[t][j][i] = 0.0f;

    const int rw = tid >> 3, ch = tid & 7;

    auto ISSUE = [&](int c) {
        const int ke = (c << 6) + ch * 8;
        const unsigned sb = smb + (c & 1) * 32768;
#pragma unroll
        for (int it = 0; it < 4; it++) {
            int r = rw + it * 32;
            unsigned so = sb + r * 128 + ((ch ^ (r & 7)) << 4);
            cpa(so, Ab + (size_t)(m0 + r) * rA + ke);
            cpa(so + 16384, Bb + (size_t)(n0 + r) * rB + ke);
        }
        asm volatile("cp.async.commit_group;" ::: "memory");
    };

    const int NC = K >> 6;
    ISSUE(0);
#pragma unroll 1
    for (int c = 0; c < NC; c++) {
        if (c + 1 < NC) {
            ISSUE(c + 1);
            asm volatile("cp.async.wait_group 1;" ::: "memory");
        } else {
            asm volatile("cp.async.wait_group 0;" ::: "memory");
        }
        __syncthreads();
        const unsigned ab = smb + (c & 1) * 32768;
#pragma unroll
        for (int ks = 0; ks < 4; ks++) {
            const unsigned cc = (unsigned)(ks * 2 + lh);
            unsigned Af[2][4], Bf[4][4];
#pragma unroll
            for (int t = 0; t < 2; t++) {
                int row = wm + 16 * t + l15;
                ldsm4(Af[t], ab + row * 128 + ((cc ^ (row & 7)) << 4));
            }
#pragma unroll
            for (int nt = 0; nt < 4; nt++) {
                int row = wn + 16 * nt + l15;
                ldsm4(Bf[nt], ab + 16384 + row * 128 + ((cc ^ (row & 7)) << 4));
            }
#pragma unroll
            for (int t = 0; t < 2; t++)
#pragma unroll
                for (int nt = 0; nt < 4; nt++)
#pragma unroll
                    for (int s = 0; s < 2; s++)
                        mma_f16(acc[t][nt * 2 + s], Af[t], Bf[nt][s], Bf[nt][2 + s]);
        }
        __syncthreads();
    }

    float* Dp = D + (size_t)bz * sD;
#pragma unroll
    for (int t = 0; t < 2; t++) {
#pragma unroll
        for (int j = 0; j < 8; j++) {
            int r0 = m0 + wm + 16 * t + (lane >> 2);
            int col = n0 + wn + 8 * j + 2 * (lane & 3);
            *(float2*)(Dp + (size_t)r0 * oS + col) =
                make_float2(acc[t][j][0], acc[t][j][1]);
            *(float2*)(Dp + (size_t)(r0 + 8) * oS + col) =
                make_float2(acc[t][j][2], acc[t][j][3]);
        }
    }
}

// ---------------------------------------------------------------------------
// Row softmax over NK with scale 1/16; emits probs as fp16
// ---------------------------------------------------------------------------
__global__ void softmax_kernel(const float* __restrict__ s, __half* __restrict__ pF) {
    size_t row = blockIdx.x;
    const float* p = s + row * (size_t)NK;
    int t = threadIdx.x;
    float v[8];
#pragma unroll
    for (int i = 0; i < 8; i++) v[i] = p[t + 256 * i] * 0.0625f;
    float mx = v[0];
#pragma unroll
    for (int i = 1; i < 8; i++) mx = fmaxf(mx, v[i]);
#pragma unroll
    for (int o = 16; o > 0; o >>= 1) mx = fmaxf(mx, __shfl_xor_sync(0xffffffffu, mx, o));
    __shared__ float redm[8], reds[8];
    if ((t & 31) == 0) redm[t >> 5] = mx;
    __syncthreads();
    float m2 = redm[0];
#pragma unroll
    for (int i = 1; i < 8; i++) m2 = fmaxf(m2, redm[i]);
    float sum = 0.0f;
#pragma unroll
    for (int i = 0; i < 8; i++) { v[i] = __expf(v[i] - m2); sum += v[i]; }
#pragma unroll
    for (int o = 16; o > 0; o >>= 1) sum += __shfl_xor_sync(0xffffffffu, sum, o);
    if ((t & 31) == 0) reds[t >> 5] = sum;
    __syncthreads();
    float s2 = 0.0f;
#pragma unroll
    for (int i = 0; i < 8; i++) s2 += reds[i];
    float inv = 1.0f / s2;
    size_t base = row * (size_t)NK + t;
#pragma unroll
    for (int i = 0; i < 8; i++)
        pF[base + 256 * i] = __float2half_rn(v[i] * inv);
}

// ---------------------------------------------------------------------------
// combine split-K partials + mirror: out[b][m]=v, out[b][2048-m]=v (m=1..1023).
// grid (1025, BB): m=1024 written once (self-mirror).
// ---------------------------------------------------------------------------
__global__ void combine_kernel(const float* __restrict__ op, float* __restrict__ out) {
    int m = blockIdx.x, b = blockIdx.y, d = threadIdx.x;
    size_t src = ((size_t)b * MP + m) * DD + d;
    float v = op[src] + op[src + (size_t)8 * MP * DD];
    out[((size_t)b * NQ + m) * DD + d] = v;
    if (m >= 1 && m <= 1023)
        out[((size_t)b * NQ + 2048 - m) * DD + d] = v;
}

// ---------------------------------------------------------------------------
extern "C" void kernel_launch(void* const* d_in, const int* in_sizes, int n_in,
                              void* d_out, int out_size) {
    const float* query = (const float*)d_in[0];
    const float* key   = (const float*)d_in[1];
    const float* Wq    = (const float*)d_in[2];
    const float* bq    = (const float*)d_in[3];
    const float* Wk    = (const float*)d_in[4];
    const float* bk    = (const float*)d_in[5];
    float* out = (float*)d_out;

#define SYM(p, s) void* p; cudaGetSymbolAddress(&p, s)
    SYM(CeH, g_CeH); SYM(CeL, g_CeL); SYM(CoH, g_CoH); SYM(CoL, g_CoL);
    SYM(qFh, g_qFh); SYM(qFl, g_qFl);
    SYM(kH, g_kH);   SYM(kL, g_kL);
    SYM(wqH, g_wqH); SYM(wqL, g_wqL); SYM(wkH, g_wkH); SYM(wkL, g_wkL);
    SYM(qpFTH, g_qpFTH); SYM(qpFTL, g_qpFTL);
    SYM(kpH, g_kpH); SYM(kpL, g_kpL);
    SYM(qfH, g_qfH); SYM(qfL, g_qfL);
    SYM(vT, g_vT);   SYM(pF, g_pF);
    SYM(sc, g_scores); SYM(op, g_op);
#undef SYM

    const int SM_64_256  = 2 * (2 * 64 * 128 + 2 * 256 * 128);   // 163840
    const int SM_128_256 = 2 * (2 * 128 * 128 + 2 * 256 * 128);  // 196608
    const int SM_64_128  = 2 * (2 * 64 * 128 + 2 * 128 * 128);   // 98304
    const int SMH = 65536;
    cudaFuncSetAttribute((const void*)gemm_kernel<1,64,256>,  cudaFuncAttributeMaxDynamicSharedMemorySize, SM_64_256);
    cudaFuncSetAttribute((const void*)gemm_kernel<1,128,256>, cudaFuncAttributeMaxDynamicSharedMemorySize, SM_128_256);
    cudaFuncSetAttribute((const void*)gemm_kernel<0,128,256>, cudaFuncAttributeMaxDynamicSharedMemorySize, SM_128_256);
    cudaFuncSetAttribute((const void*)gemm_kernel<1,64,128>,  cudaFuncAttributeMaxDynamicSharedMemorySize, SM_64_128);
    cudaFuncSetAttribute((const void*)hgemm, cudaFuncAttributeMaxDynamicSharedMemorySize, SMH);

    // preps
    cinitE_kernel<<<640, 256>>>();
    cinitO_kernel<<<576, 256>>>();
    foldsplit2_kernel<<<dim3(NFB, BB), 256>>>(query);
    split_kernel<<<16384, 256>>>(key, (bf16*)kH, (bf16*)kL, BB * NK * DD);
    splitW_kernel<<<512, 256>>>(Wq, Wk);
    transpose_kernel<<<dim3(NK / 32, DD / 32, BB), dim3(32, 8)>>>(key);

    // G1: qpFT[d, n] = Wq @ qF^T   (M=256, N=8704, K=256), 64-row tiles
    gemm_kernel<1,64,256><<<dim3(NF / 256, 4, 1), 256, SM_64_256>>>(
        (bf16*)wqH, (bf16*)wqL, 0, DD, (bf16*)qFh, (bf16*)qFl, 0, DD,
        nullptr, nullptr, (bf16*)qpFTH, (bf16*)qpFTL, 0, NF, DD, 1, 0);
    // G2: kproj = key @ Wk^T + bk  (M=16384, N=256, K=256)
    gemm_kernel<1,128,256><<<dim3(1, 128, 1), 256, SM_128_256>>>(
        (bf16*)kH, (bf16*)kL, 0, DD, (bf16*)wkH, (bf16*)wkL, 0, DD,
        bk, nullptr, (bf16*)kpH, (bf16*)kpL, 0, DD, DD, 1, 0);
    // G3e: qf[2j] = Ce @ qpFT_e^T + bq   (per b: M=640, N=256, K=576)
    gemm_kernel<1,64,128><<<dim3(2, 10, BB), 256, SM_64_128>>>(
        (bf16*)CeH, (bf16*)CeL, 0, 576, (bf16*)qpFTH, (bf16*)qpFTL, NFB, NF,
        bq, nullptr, (bf16*)qfH, (bf16*)qfL, (size_t)QFR * DD, DD, 576, 2, 0);
    // G3o: qf[2j+1] = Co @ qpFT_o^T + bq (per b: M=576, N=256, K=512)
    gemm_kernel<1,64,128><<<dim3(2, 9, BB), 256, SM_64_128>>>(
        (bf16*)CoH, (bf16*)CoL, 0, 512,
        (bf16*)qpFTH + 576, (bf16*)qpFTL + 576, NFB, NF,
        bq, nullptr, (bf16*)qfH, (bf16*)qfL, (size_t)QFR * DD, DD, 512, 2, 1);
    // G4: scores = qf @ kproj^T   (per b: M=1152, N=2048, K=256)
    gemm_kernel<0,128,256><<<dim3(8, 9, BB), 256, SM_128_256>>>(
        (bf16*)qfH, (bf16*)qfL, (size_t)QFR * DD, DD,
        (bf16*)kpH, (bf16*)kpL, (size_t)NK * DD, DD,
        nullptr, (float*)sc, nullptr, nullptr, (size_t)MP * NK, NK, DD, 1, 0);
    // softmax -> fp16 probs
    softmax_kernel<<<BB * MP, 256>>>((const float*)sc, (__half*)pF);
    // G5: partial out = probs @ vT^T (fp16, split-K=2)
    hgemm<<<dim3(2, 9, 16), 256, SMH>>>(
        (const __half*)pF, (size_t)MP * NK, NK,
        (const __half*)vT, (size_t)DD * NK, NK,
        (float*)op, (size_t)MP * DD, DD, 1024);
    // combine + mirror (row 1024 self-mirrors, written once)
    combine_kernel<<<dim3(1025, BB), 256>>>((const float*)op, out);
}

// round 14
// speedup vs baseline: 3.3923x; 1.0330x over previous
#include <cuda_runtime.h>
#include <cuda_bf16.h>
#include <cuda_fp16.h>
#include <math.h>
#include <stdint.h>

#define BB 8
#define NQ 2048
#define NK 2048
#define DD 256
#define MP 1152              // downstream row count (9*128), rows 0..1024 real+usable
#define NFB 1088             // per-batch folded rows: 576 even + 512 odd
#define NF (BB * NFB)        // 8704
#define QFR 1280             // qf buffer rows per batch
typedef __nv_bfloat16 bf16;

// ---------------- static gmem scratch ----------------
__device__ __align__(256) bf16 g_CeH[640 * 576], g_CeL[640 * 576];
__device__ __align__(256) bf16 g_CoH[576 * 512], g_CoL[576 * 512];
__device__ __align__(256) bf16 g_qFh[NF * DD], g_qFl[NF * DD];      // double-folded query
__device__ __align__(256) bf16 g_kH[BB * NK * DD], g_kL[BB * NK * DD];  // raw key split
__device__ __align__(256) bf16 g_wqH[DD * DD], g_wqL[DD * DD];
__device__ __align__(256) bf16 g_wkTH[DD * DD], g_wkTL[DD * DD];    // Wk TRANSPOSED [e][d]
__device__ __align__(256) bf16 g_qpFTH[DD * NF], g_qpFTL[DD * NF];  // qprojT [256][8704]
__device__ __align__(256) bf16 g_qfH[BB * QFR * DD], g_qfL[BB * QFR * DD];
__device__ __align__(256) bf16 g_qfkH[BB * MP * DD], g_qfkL[BB * MP * DD]; // qf @ Wk
__device__ __align__(256) __half g_vT[BB * DD * NK];                // key^T fp16
__device__ float g_scores[(size_t)BB * MP * NK];
__device__ __align__(256) __half g_pF[(size_t)BB * MP * NK];

// ---------------- helpers ----------------
__device__ __forceinline__ unsigned smem_u32(const void* p) {
    unsigned a;
    asm("{ .reg .u64 t; cvta.to.shared.u64 t, %1; cvt.u32.u64 %0, t; }"
        : "=r"(a) : "l"(p));
    return a;
}
__device__ __forceinline__ void ldsm4(unsigned r[4], unsigned addr) {
    asm volatile("ldmatrix.sync.aligned.m8n8.x4.shared.b16 {%0,%1,%2,%3}, [%4];"
                 : "=r"(r[0]), "=r"(r[1]), "=r"(r[2]), "=r"(r[3]) : "r"(addr));
}
__device__ __forceinline__ void mma_bf16(float d[4], const unsigned a[4],
                                         unsigned b0, unsigned b1) {
    asm volatile(
        "mma.sync.aligned.m16n8k16.row.col.f32.bf16.bf16.f32 "
        "{%0,%1,%2,%3}, {%4,%5,%6,%7}, {%8,%9}, {%0,%1,%2,%3};"
        : "+f"(d[0]), "+f"(d[1]), "+f"(d[2]), "+f"(d[3])
        : "r"(a[0]), "r"(a[1]), "r"(a[2]), "r"(a[3]), "r"(b0), "r"(b1));
}
__device__ __forceinline__ void mma_f16(float d[4], const unsigned a[4],
                                        unsigned b0, unsigned b1) {
    asm volatile(
        "mma.sync.aligned.m16n8k16.row.col.f32.f16.f16.f32 "
        "{%0,%1,%2,%3}, {%4,%5,%6,%7}, {%8,%9}, {%0,%1,%2,%3};"
        : "+f"(d[0]), "+f"(d[1]), "+f"(d[2]), "+f"(d[3])
        : "r"(a[0]), "r"(a[1]), "r"(a[2]), "r"(a[3]), "r"(b0), "r"(b1));
}
__device__ __forceinline__ void cpa(unsigned dst, const void* src) {
    asm volatile("cp.async.cg.shared.global [%0], [%1], 16;" :: "r"(dst), "l"(src));
}
__device__ __forceinline__ void bsplit(float v, bf16* h, bf16* l) {
    bf16 hv = __float2bfloat16(v);
    *h = hv;
    *l = __float2bfloat16(v - __bfloat162float(hv));
}

// ---------------- prep kernels ----------------
// Wq split in place; Wk split TRANSPOSED: wkT[e*256+d] = Wk[d*256+e]
__global__ void splitW_kernel(const float* __restrict__ Wq,
                              const float* __restrict__ Wk) {
    int i = blockIdx.x * blockDim.x + threadIdx.x;   // 131072
    if (i < 65536) {
        bsplit(Wq[i], &g_wqH[i], &g_wqL[i]);
    } else {
        int j = i - 65536;                 // j = d*256 + e
        int d = j >> 8, e = j & 255;
        bsplit(Wk[j], &g_wkTH[e * 256 + d], &g_wkTL[e * 256 + d]);
    }
}

// Ce[j][k] = cos(2*pi*(2j)k/2048), j<640, k<576 (real k<=512, rest harmless)
__global__ void cinitE_kernel() {
    int j = blockIdx.x;
    for (int k = threadIdx.x; k < 576; k += 256) {
        int x = (2 * j * k) & 2047;
        float c = cospif((float)x * (1.0f / 1024.0f));
        bsplit(c, &g_CeH[j * 576 + k], &g_CeL[j * 576 + k]);
    }
}
// Co[j][k] = cos(2*pi*(2j+1)k/2048), j<576, k<512
__global__ void cinitO_kernel() {
    int j = blockIdx.x;
    for (int k = threadIdx.x; k < 512; k += 256) {
        int x = ((2 * j + 1) * k) & 2047;
        float c = cospif((float)x * (1.0f / 1024.0f));
        bsplit(c, &g_CoH[j * 512 + k], &g_CoL[j * 512 + k]);
    }
}

// double fold of query along sequence:
//  even row r=k' (0..575): e[k'] = f[k'] + f[1024-k'] (e[512]=f[512]); pad>512 = 0
//  odd  row r=576+k' (k'=0..511): o[k'] = f[k'] - f[1024-k']
__global__ void foldsplit2_kernel(const float* __restrict__ query) {
    int r = blockIdx.x, b = blockIdx.y, d = threadIdx.x;
    const float* qb = query + (size_t)b * NQ * DD;
    float v;
    if (r < 576) {
        int k = r;
        if (k > 512)      v = 0.0f;
        else if (k == 0)  v = qb[d] + qb[(size_t)1024 * DD + d];
        else if (k == 512) v = qb[(size_t)512 * DD + d] + qb[(size_t)1536 * DD + d];
        else v = qb[(size_t)k * DD + d] + qb[(size_t)(2048 - k) * DD + d]
               + qb[(size_t)(1024 - k) * DD + d] + qb[(size_t)(1024 + k) * DD + d];
    } else {
        int k = r - 576;
        if (k == 0) v = qb[d] - qb[(size_t)1024 * DD + d];
        else v = qb[(size_t)k * DD + d] + qb[(size_t)(2048 - k) * DD + d]
               - qb[(size_t)(1024 - k) * DD + d] - qb[(size_t)(1024 + k) * DD + d];
    }
    size_t idx = ((size_t)b * NFB + r) * DD + d;
    bsplit(v, &g_qFh[idx], &g_qFl[idx]);
}

// fused key prep: one read of key -> kH/kL (bf16 split, [n][d]) + vT (fp16, [d][n])
__global__ void keyprep_kernel(const float* __restrict__ key) {
    __shared__ float ts[32][33];
    int b = blockIdx.z, n0 = blockIdx.x * 32, d0 = blockIdx.y * 32;
    const float* kb = key + (size_t)b * NK * DD;
#pragma unroll
    for (int i = 0; i < 4; i++) {
        int r = threadIdx.y + i * 8;
        ts[r][threadIdx.x] = kb[(size_t)(n0 + r) * DD + d0 + threadIdx.x];
    }
    __syncthreads();
#pragma unroll
    for (int i = 0; i < 4; i++) {
        int r = threadIdx.y + i * 8;
        size_t off = ((size_t)b * NK + n0 + r) * DD + d0 + threadIdx.x;
        bsplit(ts[r][threadIdx.x], &g_kH[off], &g_kL[off]);
    }
#pragma unroll
    for (int i = 0; i < 4; i++) {
        int d = threadIdx.y + i * 8;
        g_vT[(size_t)b * DD * NK + (size_t)(d0 + d) * NK + n0 + threadIdx.x] =
            __float2half_rn(ts[threadIdx.x][d]);
    }
}

// ---------------------------------------------------------------------------
// Split-bf16 mma.sync GEMM, generic CTA tile MTm x NTn (kc=64, 256 threads,
// 8 warps as 2m x 4n).  D[m,n] = sum_k A[m,k]*B[n,k] (+bias[n]).
// OUT: 0 fp32 D, 1 bf16 hi/lo.  Output row = radd + rmul*(logical row).
// ---------------------------------------------------------------------------
template<int OUT, int MT, int NT>
__global__ void __launch_bounds__(256, 1)
gemm_kernel(const bf16* __restrict__ AH, const bf16* __restrict__ AL,
            size_t sA, int rA,
            const bf16* __restrict__ BH, const bf16* __restrict__ BL,
            size_t sB, int rB,
            const float* __restrict__ bias,
            float* __restrict__ D, bf16* __restrict__ DH, bf16* __restrict__ DL,
            size_t sD, int oS, int K, int rmul, int radd)
{
    constexpr int TM   = MT / 32;
    constexpr int NJ   = NT / 32;
    constexpr int NBL  = NT / 64;
    constexpr int ABY  = MT * 128;
    constexpr int BBY  = NT * 128;
    constexpr int BUFS = 2 * ABY + 2 * BBY;

    extern __shared__ char sm[];
    const unsigned smb = smem_u32(sm);
    const int tid = threadIdx.x;
    const int lane = tid & 31;
    const int wid = tid >> 5;
    const int m0 = blockIdx.y * MT;
    const int n0 = blockIdx.x * NT;
    const int b  = blockIdx.z;
    const int wm = (wid & 1) * (MT / 2);
    const int wn = (wid >> 1) * (NT / 4);
    const int l15 = lane & 15;
    const int lh = lane >> 4;

    const bf16* AHb = AH + b * sA;
    const bf16* ALb = AL + b * sA;
    const bf16* BHb = BH + b * sB;
    const bf16* BLb = BL + b * sB;

    float acc[TM][NJ][4];
#pragma unroll
    for (int t = 0; t < TM; t++)
#pragma unroll
        for (int j = 0; j < NJ; j++)
#pragma unroll
            for (int i = 0; i < 4; i++) acc[t][j][i] = 0.0f;

    const int rw = tid >> 3, ch = tid & 7;

    auto ISSUE = [&](int c) {
        const int ke = (c << 6) + ch * 8;
        const unsigned bufb = smb + (c & 1) * BUFS;
#pragma unroll
        for (int it = 0; it < MT / 32; it++) {
            int r = rw + it * 32;
            unsigned so = bufb + r * 128 + ((ch ^ (r & 7)) << 4);
            size_t go = (size_t)(m0 + r) * rA + ke;
            cpa(so, AHb + go);
            cpa(so + ABY, ALb + go);
        }
#pragma unroll
        for (int it = 0; it < NT / 32; it++) {
            int r = rw + it * 32;
            unsigned so = bufb + 2 * ABY + r * 128 + ((ch ^ (r & 7)) << 4);
            size_t go = (size_t)(n0 + r) * rB + ke;
            cpa(so, BHb + go);
            cpa(so + BBY, BLb + go);
        }
        asm volatile("cp.async.commit_group;" ::: "memory");
    };

    const int NC = K >> 6;
    ISSUE(0);
#pragma unroll 1
    for (int c = 0; c < NC; c++) {
        if (c + 1 < NC) {
            ISSUE(c + 1);
            asm volatile("cp.async.wait_group 1;" ::: "memory");
        } else {
            asm volatile("cp.async.wait_group 0;" ::: "memory");
        }
        __syncthreads();
        const unsigned ab = smb + (c & 1) * BUFS;
#pragma unroll
        for (int ks = 0; ks < 4; ks++) {
            const unsigned cc = (unsigned)(ks * 2 + lh);
            unsigned Ah[TM][4], Al[TM][4], Bh[NBL][4], Bl[NBL][4];
#pragma unroll
            for (int t = 0; t < TM; t++) {
                int row = wm + 16 * t + l15;
                unsigned so = ab + row * 128 + ((cc ^ (row & 7)) << 4);
                ldsm4(Ah[t], so);
                ldsm4(Al[t], so + ABY);
            }
#pragma unroll
            for (int nt = 0; nt < NBL; nt++) {
                int row = wn + 16 * nt + l15;
                unsigned so = ab + 2 * ABY + row * 128 + ((cc ^ (row & 7)) << 4);
                ldsm4(Bh[nt], so);
                ldsm4(Bl[nt], so + BBY);
            }
#pragma unroll
            for (int t = 0; t < TM; t++)
#pragma unroll
                for (int nt = 0; nt < NBL; nt++)
#pragma unroll
                    for (int s = 0; s < 2; s++) {
                        int j = nt * 2 + s;
                        mma_bf16(acc[t][j], Ah[t], Bh[nt][s], Bh[nt][2 + s]);
                        mma_bf16(acc[t][j], Ah[t], Bl[nt][s], Bl[nt][2 + s]);
                        mma_bf16(acc[t][j], Al[t], Bh[nt][s], Bh[nt][2 + s]);
                    }
        }
        __syncthreads();
    }

    // ---- epilogue ----
#pragma unroll
    for (int t = 0; t < TM; t++) {
#pragma unroll
        for (int j = 0; j < NJ; j++) {
            int jr = m0 + wm + 16 * t + (lane >> 2);
            int col = n0 + wn + 8 * j + 2 * (lane & 3);
            size_t ro0 = (size_t)(radd + rmul * jr);
            size_t ro1 = (size_t)(radd + rmul * (jr + 8));
            float b0v = 0.0f, b1v = 0.0f;
            if (bias) { b0v = __ldg(&bias[col]); b1v = __ldg(&bias[col + 1]); }
            float v0 = acc[t][j][0] + b0v, v1 = acc[t][j][1] + b1v;
            float v2 = acc[t][j][2] + b0v, v3 = acc[t][j][3] + b1v;
            if (OUT == 0) {
                float* Dp = D + b * sD;
                *(float2*)(Dp + ro0 * oS + col) = make_float2(v0, v1);
                *(float2*)(Dp + ro1 * oS + col) = make_float2(v2, v3);
            } else {
                bf16* Hp = DH + b * sD;
                bf16* Lp = DL + b * sD;
                __nv_bfloat162 h01, h23, l01, l23;
                h01.x = __float2bfloat16(v0); h01.y = __float2bfloat16(v1);
                h23.x = __float2bfloat16(v2); h23.y = __float2bfloat16(v3);
                l01.x = __float2bfloat16(v0 - __bfloat162float(h01.x));
                l01.y = __float2bfloat16(v1 - __bfloat162float(h01.y));
                l23.x = __float2bfloat16(v2 - __bfloat162float(h23.x));
                l23.y = __float2bfloat16(v3 - __bfloat162float(h23.y));
                *(__nv_bfloat162*)(Hp + ro0 * oS + col) = h01;
                *(__nv_bfloat162*)(Lp + ro0 * oS + col) = l01;
                *(__nv_bfloat162*)(Hp + ro1 * oS + col) = h23;
                *(__nv_bfloat162*)(Lp + ro1 * oS + col) = l23;
            }
        }
    }
}

// ---------------------------------------------------------------------------
// fp16 single-pass GEMM for PV (post-softmax), K=2048 full (no split-K).
// CTA 128x128, kc=64, 256 thr, 8 warps 4m x 2n (32x64).
// Writes fp32 out directly WITH mirror: rows m<=1024 stored, 1<=m<=1023 also
// stored at 2048-m; rows m>1024 (pad) skipped.
// ---------------------------------------------------------------------------
__global__ void __launch_bounds__(256, 1)
hgemm(const __half* __restrict__ A, size_t sAb, int rA,
      const __half* __restrict__ B, size_t sBb, int rB,
      float* __restrict__ out)
{
    extern __shared__ char sm[];
    const unsigned smb = smem_u32(sm);
    const int tid = threadIdx.x;
    const int lane = tid & 31;
    const int wid = tid >> 5;
    const int m0 = blockIdx.y * 128;
    const int n0 = blockIdx.x * 128;
    const int b  = blockIdx.z;
    const int wm = (wid & 3) * 32;
    const int wn = (wid >> 2) * 64;
    const int l15 = lane & 15;
    const int lh = lane >> 4;

    const __half* Ab = A + (size_t)b * sAb;
    const __half* Bb = B + (size_t)b * sBb;

    float acc[2][8][4];
#pragma unroll
    for (int t = 0; t < 2; t++)
#pragma unroll
        for (int j = 0; j < 8; j++)
#pragma unroll
            for (int i = 0; i < 4; i++) acc[t][j][i] = 0.0f;

    const int rw = tid >> 3, ch = tid & 7;

    auto ISSUE = [&](int c) {
        const int ke = (c << 6) + ch * 8;
        const unsigned sb = smb + (c & 1) * 32768;
#pragma unroll
        for (int it = 0; it < 4; it++) {
            int r = rw + it * 32;
            unsigned so = sb + r * 128 + ((ch ^ (r & 7)) << 4);
            cpa(so, Ab + (size_t)(m0 + r) * rA + ke);
            cpa(so + 16384, Bb + (size_t)(n0 + r) * rB + ke);
        }
        asm volatile("cp.async.commit_group;" ::: "memory");
    };

    const int NC = NK >> 6;   // 32
    ISSUE(0);
#pragma unroll 1
    for (int c = 0; c < NC; c++) {
        if (c + 1 < NC) {
            ISSUE(c + 1);
            asm volatile("cp.async.wait_group 1;" ::: "memory");
        } else {
            asm volatile("cp.async.wait_group 0;" ::: "memory");
        }
        __syncthreads();
        const unsigned ab = smb + (c & 1) * 32768;
#pragma unroll
        for (int ks = 0; ks < 4; ks++) {
            const unsigned cc = (unsigned)(ks * 2 + lh);
            unsigned Af[2][4], Bf[4][4];
#pragma unroll
            for (int t = 0; t < 2; t++) {
                int row = wm + 16 * t + l15;
                ldsm4(Af[t], ab + row * 128 + ((cc ^ (row & 7)) << 4));
            }
#pragma unroll
            for (int nt = 0; nt < 4; nt++) {
                int row = wn + 16 * nt + l15;
                ldsm4(Bf[nt], ab + 16384 + row * 128 + ((cc ^ (row & 7)) << 4));
            }
#pragma unroll
            for (int t = 0; t < 2; t++)
#pragma unroll
                for (int nt = 0; nt < 4; nt++)
#pragma unroll
                    for (int s = 0; s < 2; s++)
                        mma_f16(acc[t][nt * 2 + s], Af[t], Bf[nt][s], Bf[nt][2 + s]);
        }
        __syncthreads();
    }

    // ---- epilogue: direct store with mirror ----
    float* Op = out + (size_t)b * NQ * DD;
#pragma unroll
    for (int t = 0; t < 2; t++) {
#pragma unroll
        for (int j = 0; j < 8; j++) {
            int col = n0 + wn + 8 * j + 2 * (lane & 3);
#pragma unroll
            for (int h = 0; h < 2; h++) {
                int m = m0 + wm + 16 * t + (lane >> 2) + 8 * h;
                if (m > 1024) continue;
                float2 v = make_float2(acc[t][j][2 * h], acc[t][j][2 * h + 1]);
                *(float2*)(Op + (size_t)m * DD + col) = v;
                if (m >= 1 && m <= 1023)
                    *(float2*)(Op + (size_t)(2048 - m) * DD + col) = v;
            }
        }
    }
}

// ---------------------------------------------------------------------------
// Row softmax over NK with scale 1/16; emits probs as fp16
// ---------------------------------------------------------------------------
__global__ void softmax_kernel(const float* __restrict__ s, __half* __restrict__ pF) {
    size_t row = blockIdx.x;
    const float* p = s + row * (size_t)NK;
    int t = threadIdx.x;
    float v[8];
#pragma unroll
    for (int i = 0; i < 8; i++) v[i] = p[t + 256 * i] * 0.0625f;
    float mx = v[0];
#pragma unroll
    for (int i = 1; i < 8; i++) mx = fmaxf(mx, v[i]);
#pragma unroll
    for (int o = 16; o > 0; o >>= 1) mx = fmaxf(mx, __shfl_xor_sync(0xffffffffu, mx, o));
    __shared__ float redm[8], reds[8];
    if ((t & 31) == 0) redm[t >> 5] = mx;
    __syncthreads();
    float m2 = redm[0];
#pragma unroll
    for (int i = 1; i < 8; i++) m2 = fmaxf(m2, redm[i]);
    float sum = 0.0f;
#pragma unroll
    for (int i = 0; i < 8; i++) { v[i] = __expf(v[i] - m2); sum += v[i]; }
#pragma unroll
    for (int o = 16; o > 0; o >>= 1) sum += __shfl_xor_sync(0xffffffffu, sum, o);
    if ((t & 31) == 0) reds[t >> 5] = sum;
    __syncthreads();
    float s2 = 0.0f;
#pragma unroll
    for (int i = 0; i < 8; i++) s2 += reds[i];
    float inv = 1.0f / s2;
    size_t base = row * (size_t)NK + t;
#pragma unroll
    for (int i = 0; i < 8; i++)
        pF[base + 256 * i] = __float2half_rn(v[i] * inv);
}

// ---------------------------------------------------------------------------
extern "C" void kernel_launch(void* const* d_in, const int* in_sizes, int n_in,
                              void* d_out, int out_size) {
    const float* query = (const float*)d_in[0];
    const float* key   = (const float*)d_in[1];
    const float* Wq    = (const float*)d_in[2];
    const float* bq    = (const float*)d_in[3];
    const float* Wk    = (const float*)d_in[4];
    // bk (d_in[5]) is softmax-invariant (adds qf·bk constant per row) — unused.
    float* out = (float*)d_out;

#define SYM(p, s) void* p; cudaGetSymbolAddress(&p, s)
    SYM(CeH, g_CeH); SYM(CeL, g_CeL); SYM(CoH, g_CoH); SYM(CoL, g_CoL);
    SYM(qFh, g_qFh); SYM(qFl, g_qFl);
    SYM(kH, g_kH);   SYM(kL, g_kL);
    SYM(wqH, g_wqH); SYM(wqL, g_wqL); SYM(wkTH, g_wkTH); SYM(wkTL, g_wkTL);
    SYM(qpFTH, g_qpFTH); SYM(qpFTL, g_qpFTL);
    SYM(qfH, g_qfH); SYM(qfL, g_qfL);
    SYM(qfkH, g_qfkH); SYM(qfkL, g_qfkL);
    SYM(vT, g_vT);   SYM(pF, g_pF);
    SYM(sc, g_scores);
#undef SYM

    const int SM_64_256  = 2 * (2 * 64 * 128 + 2 * 256 * 128);   // 163840
    const int SM_128_256 = 2 * (2 * 128 * 128 + 2 * 256 * 128);  // 196608
    const int SM_64_128  = 2 * (2 * 64 * 128 + 2 * 128 * 128);   // 98304
    const int SMH = 65536;
    cudaFuncSetAttribute((const void*)gemm_kernel<1,64,256>,  cudaFuncAttributeMaxDynamicSharedMemorySize, SM_64_256);
    cudaFuncSetAttribute((const void*)gemm_kernel<1,128,256>, cudaFuncAttributeMaxDynamicSharedMemorySize, SM_128_256);
    cudaFuncSetAttribute((const void*)gemm_kernel<0,128,256>, cudaFuncAttributeMaxDynamicSharedMemorySize, SM_128_256);
    cudaFuncSetAttribute((const void*)gemm_kernel<1,64,128>,  cudaFuncAttributeMaxDynamicSharedMemorySize, SM_64_128);
    cudaFuncSetAttribute((const void*)hgemm, cudaFuncAttributeMaxDynamicSharedMemorySize, SMH);

    // preps
    cinitE_kernel<<<640, 256>>>();
    cinitO_kernel<<<576, 256>>>();
    foldsplit2_kernel<<<dim3(NFB, BB), 256>>>(query);
    splitW_kernel<<<512, 256>>>(Wq, Wk);
    keyprep_kernel<<<dim3(NK / 32, DD / 32, BB), dim3(32, 8)>>>(key);

    // G1: qpFT[d, n] = Wq @ qF^T   (M=256, N=8704, K=256)
    gemm_kernel<1,64,256><<<dim3(NF / 256, 4, 1), 256, SM_64_256>>>(
        (bf16*)wqH, (bf16*)wqL, 0, DD, (bf16*)qFh, (bf16*)qFl, 0, DD,
        nullptr, nullptr, (bf16*)qpFTH, (bf16*)qpFTL, 0, NF, DD, 1, 0);
    // G3e: qf[2j] = Ce @ qpFT_e^T + bq   (per b: M=640, N=256, K=576)
    gemm_kernel<1,64,128><<<dim3(2, 10, BB), 256, SM_64_128>>>(
        (bf16*)CeH, (bf16*)CeL, 0, 576, (bf16*)qpFTH, (bf16*)qpFTL, NFB, NF,
        bq, nullptr, (bf16*)qfH, (bf16*)qfL, (size_t)QFR * DD, DD, 576, 2, 0);
    // G3o: qf[2j+1] = Co @ qpFT_o^T + bq (per b: M=576, N=256, K=512)
    gemm_kernel<1,64,128><<<dim3(2, 9, BB), 256, SM_64_128>>>(
        (bf16*)CoH, (bf16*)CoL, 0, 512,
        (bf16*)qpFTH + 576, (bf16*)qpFTL + 576, NFB, NF,
        bq, nullptr, (bf16*)qfH, (bf16*)qfL, (size_t)QFR * DD, DD, 512, 2, 1);
    // G2': qfk = qf @ Wk   (per b: M=1152, N=256, K=256)
    //      B operand = WkT laid out [e][d] so D[m,e] = sum_d qf[m,d]*Wk[d,e]
    gemm_kernel<1,128,256><<<dim3(1, 9, BB), 256, SM_128_256>>>(
        (bf16*)qfH, (bf16*)qfL, (size_t)QFR * DD, DD,
        (bf16*)wkTH, (bf16*)wkTL, 0, DD,
        nullptr, nullptr, (bf16*)qfkH, (bf16*)qfkL, (size_t)MP * DD, DD, DD, 1, 0);
    // G4: scores = qfk @ key^T   (per b: M=1152, N=2048, K=256)
    gemm_kernel<0,128,256><<<dim3(8, 9, BB), 256, SM_128_256>>>(
        (bf16*)qfkH, (bf16*)qfkL, (size_t)MP * DD, DD,
        (bf16*)kH, (bf16*)kL, (size_t)NK * DD, DD,
        nullptr, (float*)sc, nullptr, nullptr, (size_t)MP * NK, NK, DD, 1, 0);
    // softmax -> fp16 probs
    softmax_kernel<<<BB * MP, 256>>>((const float*)sc, (__half*)pF);
    // G5: out = probs @ vT^T (fp16, K=2048, direct write + mirror)
    hgemm<<<dim3(2, 9, BB), 256, SMH>>>(
        (const __half*)pF, (size_t)MP * NK, NK,
        (const __half*)vT, (size_t)DD * NK, NK,
        out);
}